// round 13
// baseline (speedup 1.0000x reference)
#include <cuda_runtime.h>
#include <cuda_bf16.h>
#include <math.h>
#include <stdint.h>

// Problem constants
#define BB 2
#define LL 1024
#define DMODEL 768
#define DINNER 1536
#define DSTATE 16
#define DCONV 4
#define DTRANK 48
#define MTOK (BB*LL)              // 2048 token rows
#define XZW (2*DINNER)            // 3072
#define XDBLW 80

// ---------------- scratch (device globals; no allocation allowed) ------------
__device__ float g_xz[MTOK * XZW];
__device__ float g_u0[MTOK * DINNER];
__device__ float g_u1[MTOK * DINNER];
__device__ float g_xd0[MTOK * XDBLW];
__device__ float g_xd1[MTOK * XDBLW];
__device__ float g_de0[MTOK * DINNER];
__device__ float g_de1[MTOK * DINNER];
__device__ float g_p0[MTOK * DINNER];
__device__ float g_p1[MTOK * DINNER];
__device__ float g_y0[MTOK * DINNER];
__device__ float g_y1[MTOK * DINNER];
__device__ float g_yt[MTOK * DINNER];
// packed (fragment-order, tf32-rounded) weights
// layout: [ntile][kchunk][4096]: within 4096: [ks(4)][nw(16)][lane(32)][r(2)]
__device__ float g_winp [24 * 24 * 4096];   // in_proj:  N=3072, K=768
__device__ float g_woutp[ 6 * 48 * 4096];   // out_proj: N=768,  K=1536
__device__ float g_wxp0 [ 1 * 48 * 4096];   // x_proj f: N=80,   K=1536
__device__ float g_wxp1 [ 1 * 48 * 4096];
__device__ float g_wdp0 [12 *  2 * 4096];   // dt_w f:   N=1536, K=48(pad 64)
__device__ float g_wdp1 [12 *  2 * 4096];

__device__ __forceinline__ float siluf(float x) {
    return x / (1.f + __expf(-x));
}
__device__ __forceinline__ float softplusf(float x) {
    return (x > 20.f) ? x : log1pf(__expf(x));
}
__device__ __forceinline__ float tf32r(float x) {
    uint32_t u;
    asm("cvt.rna.tf32.f32 %0, %1;" : "=r"(u) : "f"(x));
    return __uint_as_float(u);
}
__device__ __forceinline__ void mma_tf32(float c[4],
                                         uint32_t a0, uint32_t a1, uint32_t a2, uint32_t a3,
                                         uint32_t b0, uint32_t b1) {
    asm volatile(
        "mma.sync.aligned.m16n8k8.row.col.f32.tf32.tf32.f32 "
        "{%0,%1,%2,%3}, {%4,%5,%6,%7}, {%8,%9}, {%0,%1,%2,%3};"
        : "+f"(c[0]), "+f"(c[1]), "+f"(c[2]), "+f"(c[3])
        : "r"(a0), "r"(a1), "r"(a2), "r"(a3), "r"(b0), "r"(b1));
}
__device__ __forceinline__ void cp_async16(uint32_t saddr, const void* g, int bytes) {
    asm volatile("cp.async.cg.shared.global [%0], [%1], 16, %2;"
                 :: "r"(saddr), "l"(g), "r"(bytes));
}
__device__ __forceinline__ void cp_commit() {
    asm volatile("cp.async.commit_group;");
}
template<int PEND>
__device__ __forceinline__ void cp_wait() {
    asm volatile("cp.async.wait_group %0;" :: "n"(PEND));
}

// ---------------- fused prep: pack weights to fragment order + zero bufs -----
#define NSEG 9
struct PrepArgs {
    const float* src[NSEG];
    float*       dst[NSEG];
    int          N[NSEG];
    int          K[NSEG];
    int          nkch[NSEG];
    int          end[NSEG];     // cumulative element counts
    int          type[NSEG];    // 0 = pack, 1 = zero
};
__global__ __launch_bounds__(256)
void prep_kernel(PrepArgs a)
{
    int idx = blockIdx.x * 256 + threadIdx.x;
    int seg = 0, start = 0;
#pragma unroll
    for (int i = 0; i < NSEG; i++) {
        if (idx >= a.end[i]) { seg = i + 1; start = a.end[i]; }
    }
    if (seg >= NSEG) return;
    int local = idx - start;
    if (a.type[seg] == 1) {
        a.dst[seg][local] = 0.f;
        return;
    }
    int block = local >> 12;
    int w     = local & 4095;
    int ks    = w >> 10;
    int nw    = (w >> 6) & 15;
    int lane  = (w >> 1) & 31;
    int r     = w & 1;
    int nkch  = a.nkch[seg];
    int ntile = block / nkch;
    int kch   = block % nkch;
    int n = ntile * 128 + nw * 8 + (lane >> 2);
    int k = kch * 32 + ks * 8 + (lane & 3) + r * 4;
    float v = 0.f;
    if (n < a.N[seg] && k < a.K[seg])
        v = tf32r(a.src[seg][(size_t)n * a.K[seg] + k]);
    a.dst[seg][local] = v;
}

// ---------------- tf32 tensor-core NT GEMM, 512 threads ----------------------
// C[m,n] = sum_k A[m,k] * Wp(frag-packed)[n,k].  BM=128, BN=128, BK=32.
// 16 warps, warp grid 4(m) x 4(n), warp tile 32x32: per k8 step 2(mt) x 4(nt)
// m16n8k8 MMAs, acc = 32 regs.  A: cp.async + XOR swizzle, tf32 at read.
// B: cp.async from fragment-packed global -> vector LDS.64.
// blockIdx.z = dir*ksplit + kchunk.  EPI=1: softplus+bias, P=exp(d*A0).
// SPLIT=1: atomicAdd into pre-zeroed C.
template<int EPI, int SPLIT>
__global__ __launch_bounds__(512)
void gemm_tc(const float* __restrict__ A0p, const float* __restrict__ A1p,
             const float* __restrict__ Wp0, const float* __restrict__ Wp1,
             float* __restrict__ C0p, float* __restrict__ C1p,
             const float* __restrict__ b0p, const float* __restrict__ b1p,
             float* __restrict__ P0p, float* __restrict__ P1p,
             const float* __restrict__ al0, const float* __restrict__ al1,
             int M, int N, int Kc,
             int lda, int ldc, int ksplit, int nkch_tot)
{
    const int dir = blockIdx.z / ksplit;
    const int kch = blockIdx.z % ksplit;
    const float* __restrict__ A    = dir ? A1p : A0p;
    const float* __restrict__ Wp   = dir ? Wp1 : Wp0;
    float* __restrict__ C          = dir ? C1p : C0p;
    const float* __restrict__ bias = dir ? b1p : b0p;
    float* __restrict__ P          = dir ? P1p : P0p;
    const float* __restrict__ alog = dir ? al1 : al0;

    extern __shared__ float smem[];
    float* As[2] = { smem,         smem + 4096 };
    float* Bs[2] = { smem + 8192,  smem + 12288 };
    float* sA0   = smem + 16384;
    uint32_t sbase = (uint32_t)__cvta_generic_to_shared(smem);

    const int tid  = threadIdx.x;
    const int warp = tid >> 5, lane = tid & 31;
    const int wm = warp & 3, wn = warp >> 2;      // 4 x 4 warp grid
    const int gid = lane >> 2, tg = lane & 3;
    const int m0 = blockIdx.y * 128, n0 = blockIdx.x * 128;
    const int kbeg = kch * Kc;

    if (EPI == 1 && tid < 128) {
        int cc = n0 + tid;
        sA0[tid] = (cc < N) ? -__expf(alog[(size_t)cc * DSTATE]) : 0.f;
    }

    // A staging descriptors (XOR-swizzled 128x32 tile): 2 slots per thread
    const float* aptr[2]; uint32_t aoff[2]; int kslot[2];
#pragma unroll
    for (int i = 0; i < 2; i++) {
        int f = tid + i * 512;              // 0..1023
        int row = f >> 3, slot = f & 7;
        kslot[i] = slot * 4;
        aoff[i] = (uint32_t)(row * 32 + (slot ^ (row & 7)) * 4) * 4u;
        aptr[i] = A + (size_t)(m0 + row) * lda + kbeg + slot * 4;
    }
    // B staging: contiguous fragment-packed 16KB blocks
    const float* bbase = Wp + ((size_t)blockIdx.x * nkch_tot + (kbeg >> 5)) * 4096;

    const int nk = (Kc + 31) / 32;

    // stage chunk 0
#pragma unroll
    for (int i = 0; i < 2; i++) {
        int f = tid + i * 512;
        bool vk = kslot[i] < Kc;
        cp_async16(sbase + aoff[i],                    aptr[i],     vk ? 16 : 0);
        cp_async16(sbase + 32768u + (uint32_t)f * 16u, bbase + f * 4, 16);
    }
    cp_commit();

    float acc[2][4][4];
#pragma unroll
    for (int mt = 0; mt < 2; mt++)
#pragma unroll
        for (int nt = 0; nt < 4; nt++)
#pragma unroll
            for (int r = 0; r < 4; r++) acc[mt][nt][r] = 0.f;

    for (int ch = 0; ch < nk; ch++) {
        int cur = ch & 1;
        if (ch + 1 < nk) {
            int kc = (ch + 1) * 32;
            uint32_t sa = sbase + (uint32_t)((ch + 1) & 1) * 16384u;
            uint32_t sb = sa + 32768u;
            const float* bnext = bbase + (size_t)(ch + 1) * 4096;
#pragma unroll
            for (int i = 0; i < 2; i++) {
                int f = tid + i * 512;
                bool vk = (kc + kslot[i]) < Kc;
                cp_async16(sa + aoff[i], aptr[i] + kc, vk ? 16 : 0);
                cp_async16(sb + (uint32_t)f * 16u, bnext + f * 4, 16);
            }
            cp_commit();
            cp_wait<1>();
        } else {
            cp_wait<0>();
        }
        __syncthreads();

        const float* __restrict__ sa = As[cur];
        const float* __restrict__ sb = Bs[cur];
#pragma unroll
        for (int ks = 0; ks < 4; ks++) {
            int s0 = (ks * 2) ^ gid;
            int s1 = s0 ^ 1;
            uint32_t af[2][4];
#pragma unroll
            for (int mt = 0; mt < 2; mt++) {
                int r = (wm * 32 + mt * 16 + gid) * 32;
                af[mt][0] = __float_as_uint(tf32r(sa[r       + s0 * 4 + tg]));
                af[mt][1] = __float_as_uint(tf32r(sa[r + 256 + s0 * 4 + tg]));
                af[mt][2] = __float_as_uint(tf32r(sa[r       + s1 * 4 + tg]));
                af[mt][3] = __float_as_uint(tf32r(sa[r + 256 + s1 * 4 + tg]));
            }
            float2 bf[4];
#pragma unroll
            for (int nt = 0; nt < 4; nt++)
                bf[nt] = *(const float2*)&sb[((ks * 16 + wn * 4 + nt) * 32 + lane) * 2];
#pragma unroll
            for (int mt = 0; mt < 2; mt++)
#pragma unroll
                for (int nt = 0; nt < 4; nt++)
                    mma_tf32(acc[mt][nt], af[mt][0], af[mt][1], af[mt][2], af[mt][3],
                             __float_as_uint(bf[nt].x), __float_as_uint(bf[nt].y));
        }
        __syncthreads();
    }

    // epilogue
#pragma unroll
    for (int mt = 0; mt < 2; mt++) {
        int r0 = m0 + wm * 32 + mt * 16 + gid;
#pragma unroll
        for (int nt = 0; nt < 4; nt++) {
            int cc = n0 + (wn * 4 + nt) * 8 + tg * 2;
#pragma unroll
            for (int jj = 0; jj < 2; jj++) {
                int gn = cc + jj;
                if (gn >= N) continue;
                float v0 = acc[mt][nt][jj];
                float v1 = acc[mt][nt][2 + jj];
                if (EPI == 1) {
                    float bv = bias[gn];
                    float a0 = sA0[gn - n0];
                    float d0 = softplusf(v0 + bv);
                    float d1 = softplusf(v1 + bv);
                    C[(size_t)r0 * ldc + gn]       = d0;
                    C[(size_t)(r0 + 8) * ldc + gn] = d1;
                    P[(size_t)r0 * ldc + gn]       = __expf(d0 * a0);
                    P[(size_t)(r0 + 8) * ldc + gn] = __expf(d1 * a0);
                } else if (SPLIT == 1) {
                    atomicAdd(&C[(size_t)r0 * ldc + gn], v0);
                    atomicAdd(&C[(size_t)(r0 + 8) * ldc + gn], v1);
                } else {
                    C[(size_t)r0 * ldc + gn]       = v0;
                    C[(size_t)(r0 + 8) * ldc + gn] = v1;
                }
            }
        }
    }
}
#define GEMM_SMEM 66048

// ------ depthwise causal (fwd) + anti-causal (rev) conv + silu, float4 -------
__global__ void conv_silu_kernel(const float* __restrict__ xz,
                                 const float* __restrict__ wf, const float* __restrict__ bf,
                                 const float* __restrict__ wr, const float* __restrict__ br,
                                 float* __restrict__ uf, float* __restrict__ ur)
{
    int v = blockIdx.x * blockDim.x + threadIdx.x;
    const int ND4 = DINNER / 4;
    if (v >= MTOK * ND4) return;
    int d4 = v % ND4;
    int t  = (v / ND4) % LL;
    int b  = v / (ND4 * LL);
    int d  = d4 * 4;

    const float* base = xz + (size_t)b * LL * XZW + d;

    float4 Wf[4], Wr[4];
#pragma unroll
    for (int j = 0; j < 4; j++) {
        Wf[j] = *(const float4*)&wf[(d + j) * DCONV];
        Wr[j] = *(const float4*)&wr[(d + j) * DCONV];
    }
    float4 accf = *(const float4*)&bf[d];
    float4 accr = *(const float4*)&br[d];

#pragma unroll
    for (int k = 0; k < DCONV; k++) {
        int tf = t - (DCONV - 1) + k;
        int tr = t + (DCONV - 1) - k;
        float4 vf = (tf >= 0) ? *(const float4*)(base + (size_t)tf * XZW)
                              : make_float4(0.f, 0.f, 0.f, 0.f);
        float4 vr = (tr < LL) ? *(const float4*)(base + (size_t)tr * XZW)
                              : make_float4(0.f, 0.f, 0.f, 0.f);
        const float wfk[4] = { ((const float*)&Wf[0])[k], ((const float*)&Wf[1])[k],
                               ((const float*)&Wf[2])[k], ((const float*)&Wf[3])[k] };
        const float wrk[4] = { ((const float*)&Wr[0])[k], ((const float*)&Wr[1])[k],
                               ((const float*)&Wr[2])[k], ((const float*)&Wr[3])[k] };
        accf.x = fmaf(wfk[0], vf.x, accf.x);
        accf.y = fmaf(wfk[1], vf.y, accf.y);
        accf.z = fmaf(wfk[2], vf.z, accf.z);
        accf.w = fmaf(wfk[3], vf.w, accf.w);
        accr.x = fmaf(wrk[0], vr.x, accr.x);
        accr.y = fmaf(wrk[1], vr.y, accr.y);
        accr.z = fmaf(wrk[2], vr.z, accr.z);
        accr.w = fmaf(wrk[3], vr.w, accr.w);
    }
    size_t o = (size_t)(b * LL + t) * DINNER + d;
    *(float4*)&uf[o] = make_float4(siluf(accf.x), siluf(accf.y), siluf(accf.z), siluf(accf.w));
    *(float4*)&ur[o] = make_float4(siluf(accr.x), siluf(accr.y), siluf(accr.z), siluf(accr.w));
}

// ---------------- selective scan, smem-staged ---------------------------------
#define SCH  32
#define SCHN 32
__global__ __launch_bounds__(128)
void scan_kernel(const float* __restrict__ de0p, const float* __restrict__ de1p,
                 const float* __restrict__ gp0,  const float* __restrict__ gp1,
                 const float* __restrict__ xd0p, const float* __restrict__ xd1p,
                 const float* __restrict__ u0p,  const float* __restrict__ u1p,
                 const float* __restrict__ alf,  const float* __restrict__ alr,
                 const float* __restrict__ Dfp,  const float* __restrict__ Drp,
                 float* __restrict__ y0p, float* __restrict__ y1p)
{
    const int reverse = blockIdx.z;
    const float* __restrict__ delta = reverse ? de1p : de0p;
    const float* __restrict__ gp    = reverse ? gp1  : gp0;
    const float* __restrict__ xdbl  = reverse ? xd1p : xd0p;
    const float* __restrict__ u     = reverse ? u1p  : u0p;
    const float* __restrict__ A_log = reverse ? alr  : alf;
    const float* __restrict__ Dp    = reverse ? Drp  : Dfp;
    float* __restrict__ y           = reverse ? y1p  : y0p;

    __shared__ float sBC[SCH][32];
    __shared__ float sP [SCH][SCHN];
    __shared__ float sDL[SCH][SCHN];
    __shared__ float sU [SCH][SCHN];
    __shared__ float sY [SCH][SCHN];

    const int tid = threadIdx.x;
    const int ch = tid >> 2, tq = tid & 3;
    const int lane = tid & 31;
    const int d0 = blockIdx.x * SCHN;
    const int d = d0 + ch;
    const int b = blockIdx.y;

    float A[4];
#pragma unroll
    for (int j = 0; j < 4; j++)
        A[j] = -__expf(A_log[(size_t)d * DSTATE + tq * 4 + j]);
    float A0 = -__expf(A_log[(size_t)d * DSTATE]);
    bool okl = true;
#pragma unroll
    for (int j = 0; j < 4; j++) {
        float t = (float)(tq * 4 + j + 1) * A0;
        okl = okl && (fabsf(A[j] - t) <= 1e-3f * fabsf(A[j]) + 1e-6f);
    }
    unsigned bal = __ballot_sync(0xffffffffu, okl);
    int qsh = lane & 28;
    bool ok = ((bal >> qsh) & 0xFu) == 0xFu;
    float Dv = Dp[d];

    float h[4] = {0.f, 0.f, 0.f, 0.f};

    for (int c = 0; c < LL / SCH; c++) {
        __syncthreads();
#pragma unroll
        for (int k = 0; k < 2; k++) {
            int fi = tid + k * 128;
            int i  = fi >> 3;
            int qq = fi & 7;
            int tt = reverse ? (LL - 1 - (c * SCH + i)) : (c * SCH + i);
            size_t rb = (size_t)(b * LL + tt) * DINNER + d0 + qq * 4;
            *(float4*)&sP [i][qq * 4] = *(const float4*)&gp[rb];
            *(float4*)&sDL[i][qq * 4] = *(const float4*)&delta[rb];
            *(float4*)&sU [i][qq * 4] = *(const float4*)&u[rb];
            *(float4*)&sBC[i][qq * 4] =
                *(const float4*)&xdbl[(size_t)(b * LL + tt) * XDBLW + DTRANK + qq * 4];
        }
        __syncthreads();

        float pp = sP[0][ch], dl = sDL[0][ch], uu = sU[0][ch];
        float4 Bv = *(const float4*)&sBC[0][tq * 4];
        float4 Cv = *(const float4*)&sBC[0][16 + tq * 4];

        for (int i = 0; i < SCH; i++) {
            float ppn = 0.f, dln = 0.f, uun = 0.f;
            float4 Bn = Bv, Cn = Cv;
            if (i + 1 < SCH) {
                ppn = sP[i + 1][ch]; dln = sDL[i + 1][ch]; uun = sU[i + 1][ch];
                Bn = *(const float4*)&sBC[i + 1][tq * 4];
                Cn = *(const float4*)&sBC[i + 1][16 + tq * 4];
            }
            float du = dl * uu;
            float acc;
            if (ok) {
                float p2 = pp * pp;
                float p3 = p2 * pp;
                float p4 = p2 * p2;
                float p8 = p4 * p4;
                float p12 = p8 * p4;
                float q4 = (tq == 0) ? 1.f : (tq == 1) ? p4 : (tq == 2) ? p8 : p12;
                h[0] = fmaf(q4 * pp, h[0], du * Bv.x);
                h[1] = fmaf(q4 * p2, h[1], du * Bv.y);
                h[2] = fmaf(q4 * p3, h[2], du * Bv.z);
                h[3] = fmaf(q4 * p4, h[3], du * Bv.w);
            } else {
                h[0] = fmaf(__expf(dl * A[0]), h[0], du * Bv.x);
                h[1] = fmaf(__expf(dl * A[1]), h[1], du * Bv.y);
                h[2] = fmaf(__expf(dl * A[2]), h[2], du * Bv.z);
                h[3] = fmaf(__expf(dl * A[3]), h[3], du * Bv.w);
            }
            acc = h[0] * Cv.x;
            acc = fmaf(h[1], Cv.y, acc);
            acc = fmaf(h[2], Cv.z, acc);
            acc = fmaf(h[3], Cv.w, acc);
            acc += __shfl_xor_sync(0xffffffffu, acc, 1);
            acc += __shfl_xor_sync(0xffffffffu, acc, 2);
            if (tq == 0) sY[i][ch] = acc + uu * Dv;
            pp = ppn; dl = dln; uu = uun; Bv = Bn; Cv = Cn;
        }
        __syncthreads();
#pragma unroll
        for (int k = 0; k < 2; k++) {
            int fi = tid + k * 128;
            int i  = fi >> 3;
            int qq = fi & 7;
            int tt = reverse ? (LL - 1 - (c * SCH + i)) : (c * SCH + i);
            *(float4*)&y[(size_t)(b * LL + tt) * DINNER + d0 + qq * 4] =
                *(const float4*)&sY[i][qq * 4];
        }
    }
}

// ---------------- gate + sum both directions, float4 --------------------------
__global__ void combine_kernel(const float* __restrict__ xz,
                               const float* __restrict__ ya,
                               const float* __restrict__ yb,
                               float* __restrict__ yt)
{
    int v = blockIdx.x * blockDim.x + threadIdx.x;
    const int ND4 = DINNER / 4;
    if (v >= MTOK * ND4) return;
    int d4 = v % ND4;
    int m  = v / ND4;
    float4 z  = *(const float4*)&xz[(size_t)m * XZW + DINNER + d4 * 4];
    float4 a  = *(const float4*)&ya[(size_t)m * DINNER + d4 * 4];
    float4 bb = *(const float4*)&yb[(size_t)m * DINNER + d4 * 4];
    float4 o;
    o.x = siluf(z.x) * (a.x + bb.x);
    o.y = siluf(z.y) * (a.y + bb.y);
    o.z = siluf(z.z) * (a.z + bb.z);
    o.w = siluf(z.w) * (a.w + bb.w);
    *(float4*)&yt[(size_t)m * DINNER + d4 * 4] = o;
}

// ---------------- launch -----------------------------------------------------
extern "C" void kernel_launch(void* const* d_in, const int* in_sizes, int n_in,
                              void* d_out, int out_size)
{
    const float* x       = (const float*)d_in[0];
    const float* in_w    = (const float*)d_in[1];
    const float* out_w   = (const float*)d_in[2];
    const float* conv_wf = (const float*)d_in[3];
    const float* conv_bf = (const float*)d_in[4];
    const float* xproj_f = (const float*)d_in[5];
    const float* dt_wf   = (const float*)d_in[6];
    const float* dt_bf   = (const float*)d_in[7];
    const float* alog_f  = (const float*)d_in[8];
    const float* D_f     = (const float*)d_in[9];
    const float* conv_wr = (const float*)d_in[10];
    const float* conv_br = (const float*)d_in[11];
    const float* xproj_r = (const float*)d_in[12];
    const float* dt_wr   = (const float*)d_in[13];
    const float* dt_br   = (const float*)d_in[14];
    const float* alog_r  = (const float*)d_in[15];
    const float* D_r     = (const float*)d_in[16];

    float *xz, *u0, *u1, *xd0, *xd1, *de0, *de1, *p0, *p1, *y0, *y1, *yt;
    float *winp, *woutp, *wxp0, *wxp1, *wdp0, *wdp1;
    cudaGetSymbolAddress((void**)&xz,  g_xz);
    cudaGetSymbolAddress((void**)&u0,  g_u0);
    cudaGetSymbolAddress((void**)&u1,  g_u1);
    cudaGetSymbolAddress((void**)&xd0, g_xd0);
    cudaGetSymbolAddress((void**)&xd1, g_xd1);
    cudaGetSymbolAddress((void**)&de0, g_de0);
    cudaGetSymbolAddress((void**)&de1, g_de1);
    cudaGetSymbolAddress((void**)&p0,  g_p0);
    cudaGetSymbolAddress((void**)&p1,  g_p1);
    cudaGetSymbolAddress((void**)&y0,  g_y0);
    cudaGetSymbolAddress((void**)&y1,  g_y1);
    cudaGetSymbolAddress((void**)&yt,  g_yt);
    cudaGetSymbolAddress((void**)&winp,  g_winp);
    cudaGetSymbolAddress((void**)&woutp, g_woutp);
    cudaGetSymbolAddress((void**)&wxp0,  g_wxp0);
    cudaGetSymbolAddress((void**)&wxp1,  g_wxp1);
    cudaGetSymbolAddress((void**)&wdp0,  g_wdp0);
    cudaGetSymbolAddress((void**)&wdp1,  g_wdp1);

    float* out = (float*)d_out;

    cudaFuncSetAttribute(gemm_tc<0, 0>, cudaFuncAttributeMaxDynamicSharedMemorySize, GEMM_SMEM);
    cudaFuncSetAttribute(gemm_tc<0, 1>, cudaFuncAttributeMaxDynamicSharedMemorySize, GEMM_SMEM);
    cudaFuncSetAttribute(gemm_tc<1, 0>, cudaFuncAttributeMaxDynamicSharedMemorySize, GEMM_SMEM);

    // 0) fused prep: pack 6 weights (tf32, fragment order) + zero 3 buffers
    {
        PrepArgs a;
        const int c_win  = 24 * 24 * 4096;
        const int c_wout =  6 * 48 * 4096;
        const int c_wx   =  1 * 48 * 4096;
        const int c_wd   = 12 *  2 * 4096;
        const int c_xd   = MTOK * XDBLW;
        const int c_out  = MTOK * DMODEL;
        int e = 0;
        a.src[0]=in_w;    a.dst[0]=winp;  a.N[0]=XZW;    a.K[0]=DMODEL; a.nkch[0]=24; a.type[0]=0; e+=c_win;  a.end[0]=e;
        a.src[1]=out_w;   a.dst[1]=woutp; a.N[1]=DMODEL; a.K[1]=DINNER; a.nkch[1]=48; a.type[1]=0; e+=c_wout; a.end[1]=e;
        a.src[2]=xproj_f; a.dst[2]=wxp0;  a.N[2]=XDBLW;  a.K[2]=DINNER; a.nkch[2]=48; a.type[2]=0; e+=c_wx;   a.end[2]=e;
        a.src[3]=xproj_r; a.dst[3]=wxp1;  a.N[3]=XDBLW;  a.K[3]=DINNER; a.nkch[3]=48; a.type[3]=0; e+=c_wx;   a.end[3]=e;
        a.src[4]=dt_wf;   a.dst[4]=wdp0;  a.N[4]=DINNER; a.K[4]=DTRANK; a.nkch[4]=2;  a.type[4]=0; e+=c_wd;   a.end[4]=e;
        a.src[5]=dt_wr;   a.dst[5]=wdp1;  a.N[5]=DINNER; a.K[5]=DTRANK; a.nkch[5]=2;  a.type[5]=0; e+=c_wd;   a.end[5]=e;
        a.src[6]=nullptr; a.dst[6]=xd0;   a.N[6]=0; a.K[6]=0; a.nkch[6]=1; a.type[6]=1; e+=c_xd;  a.end[6]=e;
        a.src[7]=nullptr; a.dst[7]=xd1;   a.N[7]=0; a.K[7]=0; a.nkch[7]=1; a.type[7]=1; e+=c_xd;  a.end[7]=e;
        a.src[8]=nullptr; a.dst[8]=out;   a.N[8]=0; a.K[8]=0; a.nkch[8]=1; a.type[8]=1; e+=c_out; a.end[8]=e;
        prep_kernel<<<(e + 255) / 256, 256>>>(a);
    }

    // 1) xz = x @ in_proj_w^T   (2048 x 3072, K=768), shared by both dirs
    {
        dim3 grid(XZW / 128, MTOK / 128, 1);
        gemm_tc<0, 0><<<grid, 512, GEMM_SMEM>>>(x, x, winp, winp, xz, xz,
                                     nullptr, nullptr, nullptr, nullptr,
                                     nullptr, nullptr,
                                     MTOK, XZW, DMODEL, DMODEL, XZW, 1, 24);
    }
    // 2) depthwise conv + silu, both directions, float4
    {
        int n = MTOK * (DINNER / 4);
        conv_silu_kernel<<<(n + 255) / 256, 256>>>(xz, conv_wf, conv_bf,
                                                   conv_wr, conv_br, u0, u1);
    }
    // 3) x_dbl = u @ x_proj_w^T  (2048 x 80, K=1536), both dirs, split-K=4
    {
        dim3 grid(1, MTOK / 128, 2 * 4);
        gemm_tc<0, 1><<<grid, 512, GEMM_SMEM>>>(u0, u1, wxp0, wxp1, xd0, xd1,
                                     nullptr, nullptr, nullptr, nullptr,
                                     nullptr, nullptr,
                                     MTOK, XDBLW, DINNER / 4, DINNER, XDBLW, 4, 48);
    }
    // 4) delta = softplus(dt @ dt_w^T + dt_b), + p = exp(delta*A0), batched dirs
    {
        dim3 grid(DINNER / 128, MTOK / 128, 2);
        gemm_tc<1, 0><<<grid, 512, GEMM_SMEM>>>(xd0, xd1, wdp0, wdp1, de0, de1,
                                     dt_bf, dt_br, p0, p1,
                                     alog_f, alog_r,
                                     MTOK, DINNER, DTRANK, XDBLW, DINNER, 1, 2);
    }
    // 5) selective scans, smem-staged
    {
        dim3 grid(DINNER / SCHN, BB, 2);
        scan_kernel<<<grid, 128>>>(de0, de1, p0, p1, xd0, xd1, u0, u1,
                                   alog_f, alog_r, D_f, D_r, y0, y1);
    }
    // 6) gate + sum, float4
    {
        int n = MTOK * (DINNER / 4);
        combine_kernel<<<(n + 255) / 256, 256>>>(xz, y0, y1, yt);
    }
    // 7) out = y_tot @ out_proj_w^T  (2048 x 768, K=1536), split-K=2
    {
        dim3 grid(DMODEL / 128, MTOK / 128, 2);
        gemm_tc<0, 1><<<grid, 512, GEMM_SMEM>>>(yt, yt, woutp, woutp, out, out,
                                     nullptr, nullptr, nullptr, nullptr,
                                     nullptr, nullptr,
                                     MTOK, DMODEL, DINNER / 2, DINNER, DMODEL, 2, 48);
    }
}

// round 15
// speedup vs baseline: 1.0700x; 1.0700x over previous
#include <cuda_runtime.h>
#include <cuda_bf16.h>
#include <math.h>
#include <stdint.h>

// Problem constants
#define BB 2
#define LL 1024
#define DMODEL 768
#define DINNER 1536
#define DSTATE 16
#define DCONV 4
#define DTRANK 48
#define MTOK (BB*LL)              // 2048 token rows
#define XZW (2*DINNER)            // 3072
#define XDBLW 80

// ---------------- scratch (device globals; no allocation allowed) ------------
__device__ float g_xz[MTOK * XZW];
__device__ float g_u0[MTOK * DINNER];
__device__ float g_u1[MTOK * DINNER];
__device__ float g_xd0[MTOK * XDBLW];
__device__ float g_xd1[MTOK * XDBLW];
__device__ float g_de0[MTOK * DINNER];
__device__ float g_de1[MTOK * DINNER];
__device__ float g_p0[MTOK * DINNER];
__device__ float g_p1[MTOK * DINNER];
__device__ float g_y0[MTOK * DINNER];
__device__ float g_y1[MTOK * DINNER];
// packed (fragment-order, tf32-rounded) weights: [ntile][kchunk][4096]
// within 4096: [ks(4)][nw(16)][lane(32)][r(2)]
__device__ float g_winp [24 * 24 * 4096];   // in_proj:  N=3072, K=768
__device__ float g_woutp[ 6 * 48 * 4096];   // out_proj: N=768,  K=1536
__device__ float g_wxp0 [ 1 * 48 * 4096];   // x_proj f: N=80,   K=1536
__device__ float g_wxp1 [ 1 * 48 * 4096];
__device__ float g_wdp0 [12 *  2 * 4096];   // dt_w:     N=1536, K=48(pad 64)
__device__ float g_wdp1 [12 *  2 * 4096];
// fragment-order A operands: [mtile][kchunk][4096]
// within 4096: [ks(4)][mw(8)][lane(32)][reg(4)]
__device__ float g_xfrag [16 * 24 * 4096];  // x:   M=2048, K=768
__device__ float g_ytfrag[16 * 48 * 4096];  // yt:  M=2048, K=1536
__device__ float g_xdf0  [16 *  2 * 4096];  // xd dt-cols: M=2048, K=48(pad 64)
__device__ float g_xdf1  [16 *  2 * 4096];

__device__ __forceinline__ float siluf(float x) {
    return x / (1.f + __expf(-x));
}
__device__ __forceinline__ float softplusf(float x) {
    return (x > 20.f) ? x : log1pf(__expf(x));
}
__device__ __forceinline__ float tf32r(float x) {
    uint32_t u;
    asm("cvt.rna.tf32.f32 %0, %1;" : "=r"(u) : "f"(x));
    return __uint_as_float(u);
}
// A-fragment linear index for m16n8k8: value (m,k) -> packed offset
__device__ __forceinline__ int fragidx(int m, int k, int nkch) {
    int mtile = m >> 7, mw = (m >> 4) & 7, mr = m & 15;
    int kch = k >> 5, ks = (k >> 3) & 3, kc = k & 7;
    return (((mtile * nkch + kch) << 12) | (ks << 10) | (mw << 7)
            | (((mr & 7) * 4 + (kc & 3)) << 2)
            | ((mr >> 3) | ((kc >> 2) << 1)));
}
__device__ __forceinline__ void mma_tf32(float c[4],
                                         uint32_t a0, uint32_t a1, uint32_t a2, uint32_t a3,
                                         uint32_t b0, uint32_t b1) {
    asm volatile(
        "mma.sync.aligned.m16n8k8.row.col.f32.tf32.tf32.f32 "
        "{%0,%1,%2,%3}, {%4,%5,%6,%7}, {%8,%9}, {%0,%1,%2,%3};"
        : "+f"(c[0]), "+f"(c[1]), "+f"(c[2]), "+f"(c[3])
        : "r"(a0), "r"(a1), "r"(a2), "r"(a3), "r"(b0), "r"(b1));
}
__device__ __forceinline__ void cp_async16(uint32_t saddr, const void* g, int bytes) {
    asm volatile("cp.async.cg.shared.global [%0], [%1], 16, %2;"
                 :: "r"(saddr), "l"(g), "r"(bytes));
}
__device__ __forceinline__ void cp_commit() {
    asm volatile("cp.async.commit_group;");
}
template<int PEND>
__device__ __forceinline__ void cp_wait() {
    asm volatile("cp.async.wait_group %0;" :: "n"(PEND));
}

// ---------------- fused prep: pack weights + pack x + zero bufs ---------------
#define NSEG 12
struct PrepArgs {
    const float* src[NSEG];
    float*       dst[NSEG];
    int          N[NSEG];      // W-pack: N; A-pack: M rows
    int          K[NSEG];
    int          nkch[NSEG];
    int          end[NSEG];
    int          type[NSEG];   // 0 = W pack, 1 = zero, 2 = A pack
};
__global__ __launch_bounds__(256)
void prep_kernel(PrepArgs a)
{
    int idx = blockIdx.x * 256 + threadIdx.x;
    int seg = 0, start = 0;
#pragma unroll
    for (int i = 0; i < NSEG; i++) {
        if (idx >= a.end[i]) { seg = i + 1; start = a.end[i]; }
    }
    if (seg >= NSEG) return;
    int local = idx - start;
    if (a.type[seg] == 1) {
        a.dst[seg][local] = 0.f;
        return;
    }
    int block = local >> 12;
    int w     = local & 4095;
    int nkch  = a.nkch[seg];
    int tile  = block / nkch;
    int kch   = block % nkch;
    float v = 0.f;
    if (a.type[seg] == 0) {
        int ks   = w >> 10;
        int nw   = (w >> 6) & 15;
        int lane = (w >> 1) & 31;
        int r    = w & 1;
        int n = tile * 128 + nw * 8 + (lane >> 2);
        int k = kch * 32 + ks * 8 + (lane & 3) + r * 4;
        if (n < a.N[seg] && k < a.K[seg])
            v = tf32r(a.src[seg][(size_t)n * a.K[seg] + k]);
    } else { // type 2: A pack
        int ks   = w >> 10;
        int mw   = (w >> 7) & 7;
        int lane = (w >> 2) & 31;
        int reg  = w & 3;
        int m = tile * 128 + mw * 16 + (lane >> 2) + ((reg & 1) << 3);
        int k = kch * 32 + ks * 8 + (lane & 3) + ((reg >> 1) << 2);
        if (m < a.N[seg] && k < a.K[seg])
            v = tf32r(a.src[seg][(size_t)m * a.K[seg] + k]);
    }
    a.dst[seg][local] = v;
}

// ---------------- tf32 tensor-core NT GEMM ------------------------------------
// C[m,n] = sum_k A[m,k] * Wp(frag-packed)[n,k].  BM=128, BN=128, BK=32,
// 256 threads (8 warps, 4x2 warp grid, warp tile 32x64: 2(mt) x 8(nt) MMAs/k8).
// FRAGA=1: A is fragment-packed in global (like W) -> cp.async + LDS.128.
// FRAGA=0: A row-major -> cp.async + XOR swizzle + scalar LDS + tf32r.
// SPLIT: 0 plain store; 1 atomicAdd (pre-zeroed C); 2 = xd split: cols < DTRANK
// atomicAdd into fragment-packed P, cols >= DTRANK atomicAdd into normal C.
// EPI=1: softplus(acc+bias) + P=exp(delta*A0) side output.
template<int EPI, int SPLIT, int FRAGA>
__global__ __launch_bounds__(256)
void gemm_tc(const float* __restrict__ A0p, const float* __restrict__ A1p,
             const float* __restrict__ Wp0, const float* __restrict__ Wp1,
             float* __restrict__ C0p, float* __restrict__ C1p,
             const float* __restrict__ b0p, const float* __restrict__ b1p,
             float* __restrict__ P0p, float* __restrict__ P1p,
             const float* __restrict__ al0, const float* __restrict__ al1,
             int M, int N, int Kc,
             int lda, int ldc, int ksplit, int nkchW, int nkchA)
{
    const int dir = blockIdx.z / ksplit;
    const int kch = blockIdx.z % ksplit;
    const float* __restrict__ A    = dir ? A1p : A0p;
    const float* __restrict__ Wp   = dir ? Wp1 : Wp0;
    float* __restrict__ C          = dir ? C1p : C0p;
    const float* __restrict__ bias = dir ? b1p : b0p;
    float* __restrict__ P          = dir ? P1p : P0p;
    const float* __restrict__ alog = dir ? al1 : al0;

    extern __shared__ float smem[];
    float* As[2] = { smem,         smem + 4096 };
    float* Bs[2] = { smem + 8192,  smem + 12288 };
    float* sA0   = smem + 16384;
    uint32_t sbase = (uint32_t)__cvta_generic_to_shared(smem);

    const int tid  = threadIdx.x;
    const int warp = tid >> 5, lane = tid & 31;
    const int wm = warp & 3, wn = warp >> 2;
    const int gid = lane >> 2, tg = lane & 3;
    const int m0 = blockIdx.y * 128, n0 = blockIdx.x * 128;
    const int kbeg = kch * Kc;

    if (EPI == 1 && tid < 128) {
        int cc = n0 + tid;
        sA0[tid] = (cc < N) ? -__expf(alog[(size_t)cc * DSTATE]) : 0.f;
    }

    // A staging descriptors
    const float* abase = nullptr;
    const float* aptr[4]; uint32_t aoff[4]; int kslot[4];
    if (FRAGA) {
        abase = A + ((size_t)blockIdx.y * nkchA + (kbeg >> 5)) * 4096;
    } else {
#pragma unroll
        for (int i = 0; i < 4; i++) {
            int f = tid + i * 256;
            int row = f >> 3, slot = f & 7;
            kslot[i] = slot * 4;
            aoff[i] = (uint32_t)(row * 32 + (slot ^ (row & 7)) * 4) * 4u;
            aptr[i] = A + (size_t)(m0 + row) * lda + kbeg + slot * 4;
        }
    }
    const float* bbase = Wp + ((size_t)blockIdx.x * nkchW + (kbeg >> 5)) * 4096;

    const int nk = (Kc + 31) / 32;

    // stage chunk 0
#pragma unroll
    for (int i = 0; i < 4; i++) {
        int f = tid + i * 256;
        if (FRAGA) {
            cp_async16(sbase + (uint32_t)f * 16u, abase + f * 4, 16);
        } else {
            bool vk = kslot[i] < Kc;
            cp_async16(sbase + aoff[i], aptr[i], vk ? 16 : 0);
        }
        cp_async16(sbase + 32768u + (uint32_t)f * 16u, bbase + f * 4, 16);
    }
    cp_commit();

    float acc[2][8][4];
#pragma unroll
    for (int mt = 0; mt < 2; mt++)
#pragma unroll
        for (int nt = 0; nt < 8; nt++)
#pragma unroll
            for (int r = 0; r < 4; r++) acc[mt][nt][r] = 0.f;

    for (int ch = 0; ch < nk; ch++) {
        int cur = ch & 1;
        if (ch + 1 < nk) {
            int kc = (ch + 1) * 32;
            uint32_t sa = sbase + (uint32_t)((ch + 1) & 1) * 16384u;
            uint32_t sb = sa + 32768u;
            const float* bnext = bbase + (size_t)(ch + 1) * 4096;
            const float* anext = FRAGA ? (abase + (size_t)(ch + 1) * 4096) : nullptr;
#pragma unroll
            for (int i = 0; i < 4; i++) {
                int f = tid + i * 256;
                if (FRAGA) {
                    cp_async16(sa + (uint32_t)f * 16u, anext + f * 4, 16);
                } else {
                    bool vk = (kc + kslot[i]) < Kc;
                    cp_async16(sa + aoff[i], aptr[i] + kc, vk ? 16 : 0);
                }
                cp_async16(sb + (uint32_t)f * 16u, bnext + f * 4, 16);
            }
            cp_commit();
            cp_wait<1>();
        } else {
            cp_wait<0>();
        }
        __syncthreads();

        const float* __restrict__ sa = As[cur];
        const float* __restrict__ sb = Bs[cur];
#pragma unroll
        for (int ks = 0; ks < 4; ks++) {
            uint32_t af[2][4];
            if (FRAGA) {
#pragma unroll
                for (int mt = 0; mt < 2; mt++) {
                    float4 t = *(const float4*)&sa[((ks * 8 + wm * 2 + mt) * 32 + lane) * 4];
                    af[mt][0] = __float_as_uint(t.x);
                    af[mt][1] = __float_as_uint(t.y);
                    af[mt][2] = __float_as_uint(t.z);
                    af[mt][3] = __float_as_uint(t.w);
                }
            } else {
                int s0 = (ks * 2) ^ gid;
                int s1 = s0 ^ 1;
#pragma unroll
                for (int mt = 0; mt < 2; mt++) {
                    int r = (wm * 32 + mt * 16 + gid) * 32;
                    af[mt][0] = __float_as_uint(tf32r(sa[r       + s0 * 4 + tg]));
                    af[mt][1] = __float_as_uint(tf32r(sa[r + 256 + s0 * 4 + tg]));
                    af[mt][2] = __float_as_uint(tf32r(sa[r       + s1 * 4 + tg]));
                    af[mt][3] = __float_as_uint(tf32r(sa[r + 256 + s1 * 4 + tg]));
                }
            }
            float2 bf[8];
#pragma unroll
            for (int nt = 0; nt < 8; nt++)
                bf[nt] = *(const float2*)&sb[((ks * 16 + wn * 8 + nt) * 32 + lane) * 2];
#pragma unroll
            for (int mt = 0; mt < 2; mt++)
#pragma unroll
                for (int nt = 0; nt < 8; nt++)
                    mma_tf32(acc[mt][nt], af[mt][0], af[mt][1], af[mt][2], af[mt][3],
                             __float_as_uint(bf[nt].x), __float_as_uint(bf[nt].y));
        }
        __syncthreads();
    }

    // epilogue
#pragma unroll
    for (int mt = 0; mt < 2; mt++) {
        int r0 = m0 + wm * 32 + mt * 16 + gid;
#pragma unroll
        for (int nt = 0; nt < 8; nt++) {
            int cc = n0 + wn * 64 + nt * 8 + tg * 2;
#pragma unroll
            for (int jj = 0; jj < 2; jj++) {
                int gn = cc + jj;
                if (gn >= N) continue;
                float v0 = acc[mt][nt][jj];
                float v1 = acc[mt][nt][2 + jj];
                if (EPI == 1) {
                    float bv = bias[gn];
                    float a0 = sA0[gn - n0];
                    float d0 = softplusf(v0 + bv);
                    float d1 = softplusf(v1 + bv);
                    C[(size_t)r0 * ldc + gn]       = d0;
                    C[(size_t)(r0 + 8) * ldc + gn] = d1;
                    P[(size_t)r0 * ldc + gn]       = __expf(d0 * a0);
                    P[(size_t)(r0 + 8) * ldc + gn] = __expf(d1 * a0);
                } else if (SPLIT == 1) {
                    atomicAdd(&C[(size_t)r0 * ldc + gn], v0);
                    atomicAdd(&C[(size_t)(r0 + 8) * ldc + gn], v1);
                } else if (SPLIT == 2) {
                    if (gn < DTRANK) {
                        atomicAdd(&P[fragidx(r0,     gn, 2)], v0);
                        atomicAdd(&P[fragidx(r0 + 8, gn, 2)], v1);
                    } else {
                        atomicAdd(&C[(size_t)r0 * ldc + gn], v0);
                        atomicAdd(&C[(size_t)(r0 + 8) * ldc + gn], v1);
                    }
                } else {
                    C[(size_t)r0 * ldc + gn]       = v0;
                    C[(size_t)(r0 + 8) * ldc + gn] = v1;
                }
            }
        }
    }
}
#define GEMM_SMEM 66048

// ------ depthwise causal (fwd) + anti-causal (rev) conv + silu, float4 -------
__global__ void conv_silu_kernel(const float* __restrict__ xz,
                                 const float* __restrict__ wf, const float* __restrict__ bf,
                                 const float* __restrict__ wr, const float* __restrict__ br,
                                 float* __restrict__ uf, float* __restrict__ ur)
{
    int v = blockIdx.x * blockDim.x + threadIdx.x;
    const int ND4 = DINNER / 4;
    if (v >= MTOK * ND4) return;
    int d4 = v % ND4;
    int t  = (v / ND4) % LL;
    int b  = v / (ND4 * LL);
    int d  = d4 * 4;

    const float* base = xz + (size_t)b * LL * XZW + d;

    float4 Wf[4], Wr[4];
#pragma unroll
    for (int j = 0; j < 4; j++) {
        Wf[j] = *(const float4*)&wf[(d + j) * DCONV];
        Wr[j] = *(const float4*)&wr[(d + j) * DCONV];
    }
    float4 accf = *(const float4*)&bf[d];
    float4 accr = *(const float4*)&br[d];

#pragma unroll
    for (int k = 0; k < DCONV; k++) {
        int tf = t - (DCONV - 1) + k;
        int tr = t + (DCONV - 1) - k;
        float4 vf = (tf >= 0) ? *(const float4*)(base + (size_t)tf * XZW)
                              : make_float4(0.f, 0.f, 0.f, 0.f);
        float4 vr = (tr < LL) ? *(const float4*)(base + (size_t)tr * XZW)
                              : make_float4(0.f, 0.f, 0.f, 0.f);
        const float wfk[4] = { ((const float*)&Wf[0])[k], ((const float*)&Wf[1])[k],
                               ((const float*)&Wf[2])[k], ((const float*)&Wf[3])[k] };
        const float wrk[4] = { ((const float*)&Wr[0])[k], ((const float*)&Wr[1])[k],
                               ((const float*)&Wr[2])[k], ((const float*)&Wr[3])[k] };
        accf.x = fmaf(wfk[0], vf.x, accf.x);
        accf.y = fmaf(wfk[1], vf.y, accf.y);
        accf.z = fmaf(wfk[2], vf.z, accf.z);
        accf.w = fmaf(wfk[3], vf.w, accf.w);
        accr.x = fmaf(wrk[0], vr.x, accr.x);
        accr.y = fmaf(wrk[1], vr.y, accr.y);
        accr.z = fmaf(wrk[2], vr.z, accr.z);
        accr.w = fmaf(wrk[3], vr.w, accr.w);
    }
    size_t o = (size_t)(b * LL + t) * DINNER + d;
    *(float4*)&uf[o] = make_float4(siluf(accf.x), siluf(accf.y), siluf(accf.z), siluf(accf.w));
    *(float4*)&ur[o] = make_float4(siluf(accr.x), siluf(accr.y), siluf(accr.z), siluf(accr.w));
}

// ---------------- selective scan, smem-staged ---------------------------------
#define SCH  32
#define SCHN 32
__global__ __launch_bounds__(128)
void scan_kernel(const float* __restrict__ de0p, const float* __restrict__ de1p,
                 const float* __restrict__ gp0,  const float* __restrict__ gp1,
                 const float* __restrict__ xd0p, const float* __restrict__ xd1p,
                 const float* __restrict__ u0p,  const float* __restrict__ u1p,
                 const float* __restrict__ alf,  const float* __restrict__ alr,
                 const float* __restrict__ Dfp,  const float* __restrict__ Drp,
                 float* __restrict__ y0p, float* __restrict__ y1p)
{
    const int reverse = blockIdx.z;
    const float* __restrict__ delta = reverse ? de1p : de0p;
    const float* __restrict__ gp    = reverse ? gp1  : gp0;
    const float* __restrict__ xdbl  = reverse ? xd1p : xd0p;
    const float* __restrict__ u     = reverse ? u1p  : u0p;
    const float* __restrict__ A_log = reverse ? alr  : alf;
    const float* __restrict__ Dp    = reverse ? Drp  : Dfp;
    float* __restrict__ y           = reverse ? y1p  : y0p;

    __shared__ float sBC[SCH][32];
    __shared__ float sP [SCH][SCHN];
    __shared__ float sDL[SCH][SCHN];
    __shared__ float sU [SCH][SCHN];
    __shared__ float sY [SCH][SCHN];

    const int tid = threadIdx.x;
    const int ch = tid >> 2, tq = tid & 3;
    const int lane = tid & 31;
    const int d0 = blockIdx.x * SCHN;
    const int d = d0 + ch;
    const int b = blockIdx.y;

    float A[4];
#pragma unroll
    for (int j = 0; j < 4; j++)
        A[j] = -__expf(A_log[(size_t)d * DSTATE + tq * 4 + j]);
    float A0 = -__expf(A_log[(size_t)d * DSTATE]);
    bool okl = true;
#pragma unroll
    for (int j = 0; j < 4; j++) {
        float t = (float)(tq * 4 + j + 1) * A0;
        okl = okl && (fabsf(A[j] - t) <= 1e-3f * fabsf(A[j]) + 1e-6f);
    }
    unsigned bal = __ballot_sync(0xffffffffu, okl);
    int qsh = lane & 28;
    bool ok = ((bal >> qsh) & 0xFu) == 0xFu;
    float Dv = Dp[d];

    float h[4] = {0.f, 0.f, 0.f, 0.f};

    for (int c = 0; c < LL / SCH; c++) {
        __syncthreads();
#pragma unroll
        for (int k = 0; k < 2; k++) {
            int fi = tid + k * 128;
            int i  = fi >> 3;
            int qq = fi & 7;
            int tt = reverse ? (LL - 1 - (c * SCH + i)) : (c * SCH + i);
            size_t rb = (size_t)(b * LL + tt) * DINNER + d0 + qq * 4;
            *(float4*)&sP [i][qq * 4] = *(const float4*)&gp[rb];
            *(float4*)&sDL[i][qq * 4] = *(const float4*)&delta[rb];
            *(float4*)&sU [i][qq * 4] = *(const float4*)&u[rb];
            *(float4*)&sBC[i][qq * 4] =
                *(const float4*)&xdbl[(size_t)(b * LL + tt) * XDBLW + DTRANK + qq * 4];
        }
        __syncthreads();

        float pp = sP[0][ch], dl = sDL[0][ch], uu = sU[0][ch];
        float4 Bv = *(const float4*)&sBC[0][tq * 4];
        float4 Cv = *(const float4*)&sBC[0][16 + tq * 4];

        for (int i = 0; i < SCH; i++) {
            float ppn = 0.f, dln = 0.f, uun = 0.f;
            float4 Bn = Bv, Cn = Cv;
            if (i + 1 < SCH) {
                ppn = sP[i + 1][ch]; dln = sDL[i + 1][ch]; uun = sU[i + 1][ch];
                Bn = *(const float4*)&sBC[i + 1][tq * 4];
                Cn = *(const float4*)&sBC[i + 1][16 + tq * 4];
            }
            float du = dl * uu;
            float acc;
            if (ok) {
                float p2 = pp * pp;
                float p3 = p2 * pp;
                float p4 = p2 * p2;
                float p8 = p4 * p4;
                float p12 = p8 * p4;
                float q4 = (tq == 0) ? 1.f : (tq == 1) ? p4 : (tq == 2) ? p8 : p12;
                h[0] = fmaf(q4 * pp, h[0], du * Bv.x);
                h[1] = fmaf(q4 * p2, h[1], du * Bv.y);
                h[2] = fmaf(q4 * p3, h[2], du * Bv.z);
                h[3] = fmaf(q4 * p4, h[3], du * Bv.w);
            } else {
                h[0] = fmaf(__expf(dl * A[0]), h[0], du * Bv.x);
                h[1] = fmaf(__expf(dl * A[1]), h[1], du * Bv.y);
                h[2] = fmaf(__expf(dl * A[2]), h[2], du * Bv.z);
                h[3] = fmaf(__expf(dl * A[3]), h[3], du * Bv.w);
            }
            acc = h[0] * Cv.x;
            acc = fmaf(h[1], Cv.y, acc);
            acc = fmaf(h[2], Cv.z, acc);
            acc = fmaf(h[3], Cv.w, acc);
            acc += __shfl_xor_sync(0xffffffffu, acc, 1);
            acc += __shfl_xor_sync(0xffffffffu, acc, 2);
            if (tq == 0) sY[i][ch] = acc + uu * Dv;
            pp = ppn; dl = dln; uu = uun; Bv = Bn; Cv = Cn;
        }
        __syncthreads();
#pragma unroll
        for (int k = 0; k < 2; k++) {
            int fi = tid + k * 128;
            int i  = fi >> 3;
            int qq = fi & 7;
            int tt = reverse ? (LL - 1 - (c * SCH + i)) : (c * SCH + i);
            *(float4*)&y[(size_t)(b * LL + tt) * DINNER + d0 + qq * 4] =
                *(const float4*)&sY[i][qq * 4];
        }
    }
}

// -------- gate + sum both directions -> yt in A-fragment order ----------------
__global__ void combine_kernel(const float* __restrict__ xz,
                               const float* __restrict__ ya,
                               const float* __restrict__ yb,
                               float* __restrict__ ytfrag)
{
    int v = blockIdx.x * blockDim.x + threadIdx.x;
    const int ND4 = DINNER / 4;
    if (v >= MTOK * ND4) return;
    int d4 = v % ND4;
    int m  = v / ND4;
    int d  = d4 * 4;
    float4 z  = *(const float4*)&xz[(size_t)m * XZW + DINNER + d];
    float4 a  = *(const float4*)&ya[(size_t)m * DINNER + d];
    float4 bb = *(const float4*)&yb[(size_t)m * DINNER + d];
    ytfrag[fragidx(m, d + 0, 48)] = tf32r(siluf(z.x) * (a.x + bb.x));
    ytfrag[fragidx(m, d + 1, 48)] = tf32r(siluf(z.y) * (a.y + bb.y));
    ytfrag[fragidx(m, d + 2, 48)] = tf32r(siluf(z.z) * (a.z + bb.z));
    ytfrag[fragidx(m, d + 3, 48)] = tf32r(siluf(z.w) * (a.w + bb.w));
}

// ---------------- launch -----------------------------------------------------
extern "C" void kernel_launch(void* const* d_in, const int* in_sizes, int n_in,
                              void* d_out, int out_size)
{
    const float* x       = (const float*)d_in[0];
    const float* in_w    = (const float*)d_in[1];
    const float* out_w   = (const float*)d_in[2];
    const float* conv_wf = (const float*)d_in[3];
    const float* conv_bf = (const float*)d_in[4];
    const float* xproj_f = (const float*)d_in[5];
    const float* dt_wf   = (const float*)d_in[6];
    const float* dt_bf   = (const float*)d_in[7];
    const float* alog_f  = (const float*)d_in[8];
    const float* D_f     = (const float*)d_in[9];
    const float* conv_wr = (const float*)d_in[10];
    const float* conv_br = (const float*)d_in[11];
    const float* xproj_r = (const float*)d_in[12];
    const float* dt_wr   = (const float*)d_in[13];
    const float* dt_br   = (const float*)d_in[14];
    const float* alog_r  = (const float*)d_in[15];
    const float* D_r     = (const float*)d_in[16];

    float *xz, *u0, *u1, *xd0, *xd1, *de0, *de1, *p0, *p1, *y0, *y1;
    float *winp, *woutp, *wxp0, *wxp1, *wdp0, *wdp1;
    float *xfrag, *ytfrag, *xdf0, *xdf1;
    cudaGetSymbolAddress((void**)&xz,  g_xz);
    cudaGetSymbolAddress((void**)&u0,  g_u0);
    cudaGetSymbolAddress((void**)&u1,  g_u1);
    cudaGetSymbolAddress((void**)&xd0, g_xd0);
    cudaGetSymbolAddress((void**)&xd1, g_xd1);
    cudaGetSymbolAddress((void**)&de0, g_de0);
    cudaGetSymbolAddress((void**)&de1, g_de1);
    cudaGetSymbolAddress((void**)&p0,  g_p0);
    cudaGetSymbolAddress((void**)&p1,  g_p1);
    cudaGetSymbolAddress((void**)&y0,  g_y0);
    cudaGetSymbolAddress((void**)&y1,  g_y1);
    cudaGetSymbolAddress((void**)&winp,  g_winp);
    cudaGetSymbolAddress((void**)&woutp, g_woutp);
    cudaGetSymbolAddress((void**)&wxp0,  g_wxp0);
    cudaGetSymbolAddress((void**)&wxp1,  g_wxp1);
    cudaGetSymbolAddress((void**)&wdp0,  g_wdp0);
    cudaGetSymbolAddress((void**)&wdp1,  g_wdp1);
    cudaGetSymbolAddress((void**)&xfrag,  g_xfrag);
    cudaGetSymbolAddress((void**)&ytfrag, g_ytfrag);
    cudaGetSymbolAddress((void**)&xdf0,   g_xdf0);
    cudaGetSymbolAddress((void**)&xdf1,   g_xdf1);

    float* out = (float*)d_out;

    cudaFuncSetAttribute(gemm_tc<0, 0, 1>, cudaFuncAttributeMaxDynamicSharedMemorySize, GEMM_SMEM);
    cudaFuncSetAttribute(gemm_tc<0, 2, 0>, cudaFuncAttributeMaxDynamicSharedMemorySize, GEMM_SMEM);
    cudaFuncSetAttribute(gemm_tc<1, 0, 1>, cudaFuncAttributeMaxDynamicSharedMemorySize, GEMM_SMEM);
    cudaFuncSetAttribute(gemm_tc<0, 1, 1>, cudaFuncAttributeMaxDynamicSharedMemorySize, GEMM_SMEM);

    // 0) fused prep: pack 6 weights + pack x (A-frag) + zero 5 buffers
    {
        PrepArgs a;
        int e = 0;
        a.src[0]=in_w;    a.dst[0]=winp;  a.N[0]=XZW;    a.K[0]=DMODEL; a.nkch[0]=24; a.type[0]=0; e+=24*24*4096; a.end[0]=e;
        a.src[1]=out_w;   a.dst[1]=woutp; a.N[1]=DMODEL; a.K[1]=DINNER; a.nkch[1]=48; a.type[1]=0; e+=6*48*4096;  a.end[1]=e;
        a.src[2]=xproj_f; a.dst[2]=wxp0;  a.N[2]=XDBLW;  a.K[2]=DINNER; a.nkch[2]=48; a.type[2]=0; e+=1*48*4096;  a.end[2]=e;
        a.src[3]=xproj_r; a.dst[3]=wxp1;  a.N[3]=XDBLW;  a.K[3]=DINNER; a.nkch[3]=48; a.type[3]=0; e+=1*48*4096;  a.end[3]=e;
        a.src[4]=dt_wf;   a.dst[4]=wdp0;  a.N[4]=DINNER; a.K[4]=DTRANK; a.nkch[4]=2;  a.type[4]=0; e+=12*2*4096;  a.end[4]=e;
        a.src[5]=dt_wr;   a.dst[5]=wdp1;  a.N[5]=DINNER; a.K[5]=DTRANK; a.nkch[5]=2;  a.type[5]=0; e+=12*2*4096;  a.end[5]=e;
        a.src[6]=x;       a.dst[6]=xfrag; a.N[6]=MTOK;   a.K[6]=DMODEL; a.nkch[6]=24; a.type[6]=2; e+=16*24*4096; a.end[6]=e;
        a.src[7]=nullptr; a.dst[7]=xd0;   a.N[7]=0; a.K[7]=0; a.nkch[7]=1; a.type[7]=1; e+=MTOK*XDBLW;  a.end[7]=e;
        a.src[8]=nullptr; a.dst[8]=xd1;   a.N[8]=0; a.K[8]=0; a.nkch[8]=1; a.type[8]=1; e+=MTOK*XDBLW;  a.end[8]=e;
        a.src[9]=nullptr; a.dst[9]=xdf0;  a.N[9]=0; a.K[9]=0; a.nkch[9]=1; a.type[9]=1; e+=16*2*4096;   a.end[9]=e;
        a.src[10]=nullptr;a.dst[10]=xdf1; a.N[10]=0;a.K[10]=0;a.nkch[10]=1;a.type[10]=1;e+=16*2*4096;   a.end[10]=e;
        a.src[11]=nullptr;a.dst[11]=out;  a.N[11]=0;a.K[11]=0;a.nkch[11]=1;a.type[11]=1;e+=MTOK*DMODEL; a.end[11]=e;
        prep_kernel<<<(e + 255) / 256, 256>>>(a);
    }

    // 1) xz = x @ in_proj_w^T   (2048 x 3072, K=768), A frag-packed
    {
        dim3 grid(XZW / 128, MTOK / 128, 1);
        gemm_tc<0, 0, 1><<<grid, 256, GEMM_SMEM>>>(xfrag, xfrag, winp, winp, xz, xz,
                                     nullptr, nullptr, nullptr, nullptr, nullptr, nullptr,
                                     MTOK, XZW, DMODEL, 0, XZW, 1, 24, 24);
    }
    // 2) depthwise conv + silu, both directions, float4
    {
        int n = MTOK * (DINNER / 4);
        conv_silu_kernel<<<(n + 255) / 256, 256>>>(xz, conv_wf, conv_bf,
                                                   conv_wr, conv_br, u0, u1);
    }
    // 3) x_dbl = u @ x_proj_w^T  (2048 x 80, K=1536), split-K=4;
    //    dt-cols -> xd-frag (atomic), B/C-cols -> normal xd (atomic)
    {
        dim3 grid(1, MTOK / 128, 2 * 4);
        gemm_tc<0, 2, 0><<<grid, 256, GEMM_SMEM>>>(u0, u1, wxp0, wxp1, xd0, xd1,
                                     nullptr, nullptr, xdf0, xdf1, nullptr, nullptr,
                                     MTOK, XDBLW, DINNER / 4, DINNER, XDBLW, 4, 48, 0);
    }
    // 4) delta = softplus(dt @ dt_w^T + dt_b), + p = exp(delta*A0); A frag (K pad 64)
    {
        dim3 grid(DINNER / 128, MTOK / 128, 2);
        gemm_tc<1, 0, 1><<<grid, 256, GEMM_SMEM>>>(xdf0, xdf1, wdp0, wdp1, de0, de1,
                                     dt_bf, dt_br, p0, p1, alog_f, alog_r,
                                     MTOK, DINNER, 64, 0, DINNER, 1, 2, 2);
    }
    // 5) selective scans, smem-staged
    {
        dim3 grid(DINNER / SCHN, BB, 2);
        scan_kernel<<<grid, 128>>>(de0, de1, p0, p1, xd0, xd1, u0, u1,
                                   alog_f, alog_r, D_f, D_r, y0, y1);
    }
    // 6) gate + sum -> yt (A-fragment order)
    {
        int n = MTOK * (DINNER / 4);
        combine_kernel<<<(n + 255) / 256, 256>>>(xz, y0, y1, ytfrag);
    }
    // 7) out = y_tot @ out_proj_w^T  (2048 x 768, K=1536), split-K=2, A frag
    {
        dim3 grid(DMODEL / 128, MTOK / 128, 2);
        gemm_tc<0, 1, 1><<<grid, 256, GEMM_SMEM>>>(ytfrag, ytfrag, woutp, woutp, out, out,
                                     nullptr, nullptr, nullptr, nullptr, nullptr, nullptr,
                                     MTOK, DMODEL, DINNER / 2, 0, DMODEL, 2, 48, 48);
    }
}